// round 1
// baseline (speedup 1.0000x reference)
#include <cuda_runtime.h>
#include <math.h>

// Problem constants
constexpr int Bb = 4;
constexpr int Ss = 2048;
constexpr int Ee = 768;
constexpr int Hh = 12;
constexpr int Dd = 64;
constexpr int Mrows = Bb * Ss;      // 8192
constexpr int N_QKV = 3 * Ee;       // 2304

// GEMM tiling
constexpr int BM = 64, BN = 64, BK = 16;

// Scratch (device globals: no allocation allowed)
__device__ float g_q[(size_t)Bb * Hh * Ss * Dd];
__device__ float g_k[(size_t)Bb * Hh * Ss * Dd];
__device__ float g_v[(size_t)Bb * Hh * Ss * Dd];
__device__ float g_y[(size_t)Bb * Ss * Ee];

// ---------------------------------------------------------------------------
// Kernel 1: QKV = x @ W_attn + b_attn, scattered to [B,H,S,D] q/k/v buffers
// ---------------------------------------------------------------------------
__global__ __launch_bounds__(256) void qkv_gemm_kernel(
    const float* __restrict__ x,      // [M, E]
    const float* __restrict__ W,      // [E, 3E]
    const float* __restrict__ bias)   // [3E]
{
    __shared__ float As[BK][BM + 1];  // stored transposed: As[k][m]
    __shared__ float Bs[BK][BN];

    const int tid = threadIdx.x;
    const int tx = tid & 15;
    const int ty = tid >> 4;
    const int m0 = blockIdx.y * BM;
    const int n0 = blockIdx.x * BN;

    float acc[4][4] = {};

    for (int k0 = 0; k0 < Ee; k0 += BK) {
        // Load A tile (64 rows x 16 k), one float4 per thread, store transposed
        {
            const int row = tid >> 2;       // 0..63
            const int seg = tid & 3;        // 0..3 (x4 floats)
            const float4 v4 = *reinterpret_cast<const float4*>(
                x + (size_t)(m0 + row) * Ee + k0 + seg * 4);
            As[seg * 4 + 0][row] = v4.x;
            As[seg * 4 + 1][row] = v4.y;
            As[seg * 4 + 2][row] = v4.z;
            As[seg * 4 + 3][row] = v4.w;
        }
        // Load B tile (16 k x 64 n), one float4 per thread
        {
            const int row = tid >> 4;       // 0..15
            const int c4 = tid & 15;        // 0..15
            const float4 v4 = *reinterpret_cast<const float4*>(
                W + (size_t)(k0 + row) * N_QKV + n0 + c4 * 4);
            Bs[row][c4 * 4 + 0] = v4.x;
            Bs[row][c4 * 4 + 1] = v4.y;
            Bs[row][c4 * 4 + 2] = v4.z;
            Bs[row][c4 * 4 + 3] = v4.w;
        }
        __syncthreads();

        #pragma unroll
        for (int kk = 0; kk < BK; kk++) {
            float a[4], bb[4];
            #pragma unroll
            for (int i = 0; i < 4; i++) a[i] = As[kk][ty * 4 + i];
            #pragma unroll
            for (int j = 0; j < 4; j++) bb[j] = Bs[kk][tx * 4 + j];
            #pragma unroll
            for (int i = 0; i < 4; i++)
                #pragma unroll
                for (int j = 0; j < 4; j++)
                    acc[i][j] = fmaf(a[i], bb[j], acc[i][j]);
        }
        __syncthreads();
    }

    // Epilogue: add bias, scatter into [B,H,S,D]
    #pragma unroll
    for (int i = 0; i < 4; i++) {
        const int m = m0 + ty * 4 + i;
        const int b = m >> 11;          // / 2048
        const int s = m & 2047;
        #pragma unroll
        for (int j = 0; j < 4; j++) {
            const int n = n0 + tx * 4 + j;
            const float val = acc[i][j] + bias[n];
            const int which = n / Ee;   // 0=q, 1=k, 2=v
            const int e = n - which * Ee;
            const int h = e >> 6;
            const int d = e & 63;
            const size_t idx = (((size_t)(b * Hh + h)) * Ss + s) * Dd + d;
            float* dst = (which == 0) ? g_q : (which == 1) ? g_k : g_v;
            dst[idx] = val;
        }
    }
}

// ---------------------------------------------------------------------------
// Kernel 2: flash-style causal attention, 64x64 tiles, online softmax
// grid: (S/64, H, B), block: 256 threads (16x16, 4x4 per thread)
// ---------------------------------------------------------------------------
constexpr int ATT_LD = 65;  // padded row stride for all smem tiles
constexpr size_t ATT_SMEM_BYTES = (size_t)4 * 64 * ATT_LD * sizeof(float);

__global__ __launch_bounds__(256) void attn_kernel(const int* __restrict__ att_mask)
{
    extern __shared__ float sm[];
    float* Qs = sm;                     // [64][65]  Qs[q][d]
    float* Ks = sm + 64 * ATT_LD;       // [64][65]  Ks[k][d]
    float* Vs = sm + 2 * 64 * ATT_LD;   // [64][65]  Vs[k][d]
    float* Ps = sm + 3 * 64 * ATT_LD;   // [64][65]  Ps[q][k]

    const int tid = threadIdx.x;
    const int tx = tid & 15;
    const int ty = tid >> 4;
    const int qb = blockIdx.x;
    const int h = blockIdx.y;
    const int b = blockIdx.z;
    const size_t head_base = ((size_t)(b * Hh + h)) * Ss * Dd;
    const int q0 = qb * 64;

    // Load Q tile [64][64] -> Qs
    #pragma unroll
    for (int p = 0; p < 4; p++) {
        const int lin = p * 256 + tid;   // float4 id 0..1023
        const int r = lin >> 4;
        const int c4 = lin & 15;
        const float4 v4 = *reinterpret_cast<const float4*>(
            g_q + head_base + (size_t)(q0 + r) * Dd + c4 * 4);
        Qs[r * ATT_LD + c4 * 4 + 0] = v4.x;
        Qs[r * ATT_LD + c4 * 4 + 1] = v4.y;
        Qs[r * ATT_LD + c4 * 4 + 2] = v4.z;
        Qs[r * ATT_LD + c4 * 4 + 3] = v4.w;
    }

    float m_i[4], l_i[4];
    float acc[4][4] = {};
    #pragma unroll
    for (int i = 0; i < 4; i++) { m_i[i] = -INFINITY; l_i[i] = 0.0f; }

    for (int j = 0; j <= qb; j++) {
        __syncthreads();  // previous O-gemm done reading Ks/Vs/Ps
        // Load K and V tiles for key rows [j*64, j*64+64)
        #pragma unroll
        for (int p = 0; p < 4; p++) {
            const int lin = p * 256 + tid;
            const int r = lin >> 4;
            const int c4 = lin & 15;
            const size_t off = head_base + (size_t)(j * 64 + r) * Dd + c4 * 4;
            const float4 k4 = *reinterpret_cast<const float4*>(g_k + off);
            const float4 v4 = *reinterpret_cast<const float4*>(g_v + off);
            Ks[r * ATT_LD + c4 * 4 + 0] = k4.x;
            Ks[r * ATT_LD + c4 * 4 + 1] = k4.y;
            Ks[r * ATT_LD + c4 * 4 + 2] = k4.z;
            Ks[r * ATT_LD + c4 * 4 + 3] = k4.w;
            Vs[r * ATT_LD + c4 * 4 + 0] = v4.x;
            Vs[r * ATT_LD + c4 * 4 + 1] = v4.y;
            Vs[r * ATT_LD + c4 * 4 + 2] = v4.z;
            Vs[r * ATT_LD + c4 * 4 + 3] = v4.w;
        }
        __syncthreads();

        // S = Q K^T (64x64), each thread 4x4
        float s[4][4] = {};
        #pragma unroll 8
        for (int kk = 0; kk < Dd; kk++) {
            float a[4], bb[4];
            #pragma unroll
            for (int i = 0; i < 4; i++) a[i] = Qs[(ty * 4 + i) * ATT_LD + kk];
            #pragma unroll
            for (int jj = 0; jj < 4; jj++) bb[jj] = Ks[(tx * 4 + jj) * ATT_LD + kk];
            #pragma unroll
            for (int i = 0; i < 4; i++)
                #pragma unroll
                for (int jj = 0; jj < 4; jj++)
                    s[i][jj] = fmaf(a[i], bb[jj], s[i][jj]);
        }

        // Scale + causal + att_mask
        const int kbase = j * 64 + tx * 4;
        int mk[4];
        #pragma unroll
        for (int jj = 0; jj < 4; jj++) mk[jj] = att_mask[b * Ss + kbase + jj];

        #pragma unroll
        for (int i = 0; i < 4; i++) {
            const int qg = q0 + ty * 4 + i;
            #pragma unroll
            for (int jj = 0; jj < 4; jj++) {
                const int kg = kbase + jj;
                s[i][jj] = (kg <= qg && mk[jj] != 0) ? s[i][jj] * 0.125f : -INFINITY;
            }
        }

        // Online softmax (row reductions across the 16 lanes sharing a q-row)
        #pragma unroll
        for (int i = 0; i < 4; i++) {
            float rm = fmaxf(fmaxf(s[i][0], s[i][1]), fmaxf(s[i][2], s[i][3]));
            #pragma unroll
            for (int off = 8; off >= 1; off >>= 1)
                rm = fmaxf(rm, __shfl_xor_sync(0xffffffffu, rm, off));
            const float mn = fmaxf(m_i[i], rm);
            const float alpha = __expf(m_i[i] - mn);   // exp(-inf)=0 on first tile
            float p[4];
            float rs = 0.0f;
            #pragma unroll
            for (int jj = 0; jj < 4; jj++) {
                p[jj] = __expf(s[i][jj] - mn);          // masked -> exp(-inf)=0
                rs += p[jj];
            }
            #pragma unroll
            for (int off = 8; off >= 1; off >>= 1)
                rs += __shfl_xor_sync(0xffffffffu, rs, off);
            l_i[i] = l_i[i] * alpha + rs;
            m_i[i] = mn;
            #pragma unroll
            for (int jj = 0; jj < 4; jj++) acc[i][jj] *= alpha;
            #pragma unroll
            for (int jj = 0; jj < 4; jj++)
                Ps[(ty * 4 + i) * ATT_LD + tx * 4 + jj] = p[jj];
        }
        __syncthreads();

        // O += P V  (64x64 x 64x64)
        #pragma unroll 8
        for (int kk = 0; kk < 64; kk++) {
            float pi[4], vj[4];
            #pragma unroll
            for (int i = 0; i < 4; i++) pi[i] = Ps[(ty * 4 + i) * ATT_LD + kk];
            #pragma unroll
            for (int jj = 0; jj < 4; jj++) vj[jj] = Vs[kk * ATT_LD + tx * 4 + jj];
            #pragma unroll
            for (int i = 0; i < 4; i++)
                #pragma unroll
                for (int jj = 0; jj < 4; jj++)
                    acc[i][jj] = fmaf(pi[i], vj[jj], acc[i][jj]);
        }
    }

    // Epilogue: O / l, write back to [B,S,E] layout in g_y
    #pragma unroll
    for (int i = 0; i < 4; i++) {
        const float inv = 1.0f / l_i[i];
        const int qg = q0 + ty * 4 + i;
        const size_t row = ((size_t)(b * Ss + qg)) * Ee + h * 64;
        #pragma unroll
        for (int jj = 0; jj < 4; jj++)
            g_y[row + tx * 4 + jj] = acc[i][jj] * inv;
    }
}

// ---------------------------------------------------------------------------
// Kernel 3: out = y @ W_proj + b_proj
// ---------------------------------------------------------------------------
__global__ __launch_bounds__(256) void proj_gemm_kernel(
    const float* __restrict__ W,      // [E, E]
    const float* __restrict__ bias,   // [E]
    float* __restrict__ out)          // [M, E]
{
    __shared__ float As[BK][BM + 1];
    __shared__ float Bs[BK][BN];

    const int tid = threadIdx.x;
    const int tx = tid & 15;
    const int ty = tid >> 4;
    const int m0 = blockIdx.y * BM;
    const int n0 = blockIdx.x * BN;

    float acc[4][4] = {};

    for (int k0 = 0; k0 < Ee; k0 += BK) {
        {
            const int row = tid >> 2;
            const int seg = tid & 3;
            const float4 v4 = *reinterpret_cast<const float4*>(
                g_y + (size_t)(m0 + row) * Ee + k0 + seg * 4);
            As[seg * 4 + 0][row] = v4.x;
            As[seg * 4 + 1][row] = v4.y;
            As[seg * 4 + 2][row] = v4.z;
            As[seg * 4 + 3][row] = v4.w;
        }
        {
            const int row = tid >> 4;
            const int c4 = tid & 15;
            const float4 v4 = *reinterpret_cast<const float4*>(
                W + (size_t)(k0 + row) * Ee + n0 + c4 * 4);
            Bs[row][c4 * 4 + 0] = v4.x;
            Bs[row][c4 * 4 + 1] = v4.y;
            Bs[row][c4 * 4 + 2] = v4.z;
            Bs[row][c4 * 4 + 3] = v4.w;
        }
        __syncthreads();

        #pragma unroll
        for (int kk = 0; kk < BK; kk++) {
            float a[4], bb[4];
            #pragma unroll
            for (int i = 0; i < 4; i++) a[i] = As[kk][ty * 4 + i];
            #pragma unroll
            for (int j = 0; j < 4; j++) bb[j] = Bs[kk][tx * 4 + j];
            #pragma unroll
            for (int i = 0; i < 4; i++)
                #pragma unroll
                for (int j = 0; j < 4; j++)
                    acc[i][j] = fmaf(a[i], bb[j], acc[i][j]);
        }
        __syncthreads();
    }

    #pragma unroll
    for (int i = 0; i < 4; i++) {
        const int m = m0 + ty * 4 + i;
        #pragma unroll
        for (int j = 0; j < 4; j++) {
            const int n = n0 + tx * 4 + j;
            out[(size_t)m * Ee + n] = acc[i][j] + bias[n];
        }
    }
}

// ---------------------------------------------------------------------------
// Launch
// ---------------------------------------------------------------------------
extern "C" void kernel_launch(void* const* d_in, const int* in_sizes, int n_in,
                              void* d_out, int out_size)
{
    const float* x      = (const float*)d_in[0];  // [B,S,E]
    const float* W_attn = (const float*)d_in[1];  // [E,3E]
    const float* b_attn = (const float*)d_in[2];  // [3E]
    const float* W_proj = (const float*)d_in[3];  // [E,E]
    const float* b_proj = (const float*)d_in[4];  // [E]
    const int* att_mask = (const int*)d_in[5];    // [B,S]
    float* out = (float*)d_out;

    // Opt-in to >48KB dynamic smem for the attention kernel (idempotent)
    cudaFuncSetAttribute(attn_kernel,
                         cudaFuncAttributeMaxDynamicSharedMemorySize,
                         (int)ATT_SMEM_BYTES);

    {
        dim3 grid(N_QKV / BN, Mrows / BM);   // 36 x 128
        qkv_gemm_kernel<<<grid, 256>>>(x, W_attn, b_attn);
    }
    {
        dim3 grid(Ss / 64, Hh, Bb);          // 32 x 12 x 4
        attn_kernel<<<grid, 256, ATT_SMEM_BYTES>>>(att_mask);
    }
    {
        dim3 grid(Ee / BN, Mrows / BM);      // 12 x 128
        proj_gemm_kernel<<<grid, 256>>>(W_proj, b_proj, out);
    }
}

// round 9
// speedup vs baseline: 1.0437x; 1.0437x over previous
#include <cuda_runtime.h>
#include <math.h>

// Problem constants
constexpr int Bb = 4;
constexpr int Ss = 2048;
constexpr int Ee = 768;
constexpr int Hh = 12;
constexpr int Dd = 64;
constexpr int Mrows = Bb * Ss;      // 8192
constexpr int N_QKV = 3 * Ee;       // 2304

// GEMM tiling
constexpr int BM = 64, BN = 64, BK = 16;

// Scratch (device globals: no allocation allowed)
__device__ float g_q[(size_t)Bb * Hh * Ss * Dd];
__device__ float g_k[(size_t)Bb * Hh * Ss * Dd];
__device__ float g_v[(size_t)Bb * Hh * Ss * Dd];
__device__ float g_y[(size_t)Bb * Ss * Ee];

// ---------------------------------------------------------------------------
// Kernel 1: QKV = x @ W_attn + b_attn, scattered to [B,H,S,D] q/k/v buffers
// (byte-identical to the R1-passing version)
// ---------------------------------------------------------------------------
__global__ __launch_bounds__(256) void qkv_gemm_kernel(
    const float* __restrict__ x,      // [M, E]
    const float* __restrict__ W,      // [E, 3E]
    const float* __restrict__ bias)   // [3E]
{
    __shared__ float As[BK][BM + 1];  // stored transposed: As[k][m]
    __shared__ float Bs[BK][BN];

    const int tid = threadIdx.x;
    const int tx = tid & 15;
    const int ty = tid >> 4;
    const int m0 = blockIdx.y * BM;
    const int n0 = blockIdx.x * BN;

    float acc[4][4] = {};

    for (int k0 = 0; k0 < Ee; k0 += BK) {
        // Load A tile (64 rows x 16 k), one float4 per thread, store transposed
        {
            const int row = tid >> 2;       // 0..63
            const int seg = tid & 3;        // 0..3 (x4 floats)
            const float4 v4 = *reinterpret_cast<const float4*>(
                x + (size_t)(m0 + row) * Ee + k0 + seg * 4);
            As[seg * 4 + 0][row] = v4.x;
            As[seg * 4 + 1][row] = v4.y;
            As[seg * 4 + 2][row] = v4.z;
            As[seg * 4 + 3][row] = v4.w;
        }
        // Load B tile (16 k x 64 n), one float4 per thread
        {
            const int row = tid >> 4;       // 0..15
            const int c4 = tid & 15;        // 0..15
            const float4 v4 = *reinterpret_cast<const float4*>(
                W + (size_t)(k0 + row) * N_QKV + n0 + c4 * 4);
            Bs[row][c4 * 4 + 0] = v4.x;
            Bs[row][c4 * 4 + 1] = v4.y;
            Bs[row][c4 * 4 + 2] = v4.z;
            Bs[row][c4 * 4 + 3] = v4.w;
        }
        __syncthreads();

        #pragma unroll
        for (int kk = 0; kk < BK; kk++) {
            float a[4], bb[4];
            #pragma unroll
            for (int i = 0; i < 4; i++) a[i] = As[kk][ty * 4 + i];
            #pragma unroll
            for (int j = 0; j < 4; j++) bb[j] = Bs[kk][tx * 4 + j];
            #pragma unroll
            for (int i = 0; i < 4; i++)
                #pragma unroll
                for (int j = 0; j < 4; j++)
                    acc[i][j] = fmaf(a[i], bb[j], acc[i][j]);
        }
        __syncthreads();
    }

    // Epilogue: add bias, scatter into [B,H,S,D]
    #pragma unroll
    for (int i = 0; i < 4; i++) {
        const int m = m0 + ty * 4 + i;
        const int b = m >> 11;          // / 2048
        const int s = m & 2047;
        #pragma unroll
        for (int j = 0; j < 4; j++) {
            const int n = n0 + tx * 4 + j;
            const float val = acc[i][j] + bias[n];
            const int which = n / Ee;   // 0=q, 1=k, 2=v
            const int e = n - which * Ee;
            const int h = e >> 6;
            const int d = e & 63;
            const size_t idx = (((size_t)(b * Hh + h)) * Ss + s) * Dd + d;
            float* dst = (which == 0) ? g_q : (which == 1) ? g_k : g_v;
            dst[idx] = val;
        }
    }
}

// ---------------------------------------------------------------------------
// Kernel 2: flash-style causal attention, 128-query x 64-key tiles.
// 256 threads (16x16), 8 rows x 4 keys per thread. Online softmax with the
// same validated 16-lane shuffle reduction as R1.
// ---------------------------------------------------------------------------
constexpr int ATT_LD = 65;
constexpr int QROWS = 128;
constexpr size_t ATT_SMEM_BYTES =
    (size_t)(QROWS * ATT_LD + 64 * ATT_LD + 64 * ATT_LD + QROWS * ATT_LD) * sizeof(float); // 99840

__global__ __launch_bounds__(256) void attn_kernel(const int* __restrict__ att_mask)
{
    extern __shared__ float sm[];
    float* Qs = sm;                                    // [128][65]
    float* Ks = sm + QROWS * ATT_LD;                   // [64][65]
    float* Vs = sm + QROWS * ATT_LD + 64 * ATT_LD;     // [64][65]
    float* Ps = sm + QROWS * ATT_LD + 2 * 64 * ATT_LD; // [128][65]

    const int tid = threadIdx.x;
    const int tx = tid & 15;
    const int ty = tid >> 4;
    const int qb = blockIdx.x;          // 0..15
    const int h = blockIdx.y;
    const int b = blockIdx.z;
    const size_t head_base = ((size_t)(b * Hh + h)) * Ss * Dd;
    const int q0 = qb * QROWS;

    // Load Q tile [128][64] -> Qs (2048 float4, 8 per thread)
    #pragma unroll
    for (int p = 0; p < 8; p++) {
        const int lin = p * 256 + tid;
        const int r = lin >> 4;
        const int c4 = lin & 15;
        const float4 v4 = *reinterpret_cast<const float4*>(
            g_q + head_base + (size_t)(q0 + r) * Dd + c4 * 4);
        Qs[r * ATT_LD + c4 * 4 + 0] = v4.x;
        Qs[r * ATT_LD + c4 * 4 + 1] = v4.y;
        Qs[r * ATT_LD + c4 * 4 + 2] = v4.z;
        Qs[r * ATT_LD + c4 * 4 + 3] = v4.w;
    }

    float m_i[8], l_i[8];
    float acc[8][4] = {};
    #pragma unroll
    for (int i = 0; i < 8; i++) { m_i[i] = -INFINITY; l_i[i] = 0.0f; }

    const int jmax = 2 * qb + 1;        // last key tile overlapping this q tile
    for (int j = 0; j <= jmax; j++) {
        __syncthreads();  // previous iteration done reading Ks/Vs/Ps
        // Load K and V tiles for key rows [j*64, j*64+64)
        #pragma unroll
        for (int p = 0; p < 4; p++) {
            const int lin = p * 256 + tid;
            const int r = lin >> 4;
            const int c4 = lin & 15;
            const size_t off = head_base + (size_t)(j * 64 + r) * Dd + c4 * 4;
            const float4 k4 = *reinterpret_cast<const float4*>(g_k + off);
            const float4 v4 = *reinterpret_cast<const float4*>(g_v + off);
            Ks[r * ATT_LD + c4 * 4 + 0] = k4.x;
            Ks[r * ATT_LD + c4 * 4 + 1] = k4.y;
            Ks[r * ATT_LD + c4 * 4 + 2] = k4.z;
            Ks[r * ATT_LD + c4 * 4 + 3] = k4.w;
            Vs[r * ATT_LD + c4 * 4 + 0] = v4.x;
            Vs[r * ATT_LD + c4 * 4 + 1] = v4.y;
            Vs[r * ATT_LD + c4 * 4 + 2] = v4.z;
            Vs[r * ATT_LD + c4 * 4 + 3] = v4.w;
        }
        __syncthreads();

        // S = Q K^T (128x64), each thread 8x4
        float s[8][4] = {};
        #pragma unroll 8
        for (int kk = 0; kk < Dd; kk++) {
            float a[8], bbk[4];
            #pragma unroll
            for (int i = 0; i < 8; i++) a[i] = Qs[(ty * 8 + i) * ATT_LD + kk];
            #pragma unroll
            for (int jj = 0; jj < 4; jj++) bbk[jj] = Ks[(tx * 4 + jj) * ATT_LD + kk];
            #pragma unroll
            for (int i = 0; i < 8; i++)
                #pragma unroll
                for (int jj = 0; jj < 4; jj++)
                    s[i][jj] = fmaf(a[i], bbk[jj], s[i][jj]);
        }

        // Scale + causal + att_mask
        const int kbase = j * 64 + tx * 4;
        int mk[4];
        #pragma unroll
        for (int jj = 0; jj < 4; jj++) mk[jj] = att_mask[b * Ss + kbase + jj];

        #pragma unroll
        for (int i = 0; i < 8; i++) {
            const int qg = q0 + ty * 8 + i;
            #pragma unroll
            for (int jj = 0; jj < 4; jj++) {
                const int kg = kbase + jj;
                s[i][jj] = (kg <= qg && mk[jj] != 0) ? s[i][jj] * 0.125f : -INFINITY;
            }
        }

        // Online softmax (reduction across the 16 lanes sharing a q-row)
        #pragma unroll
        for (int i = 0; i < 8; i++) {
            float rm = fmaxf(fmaxf(s[i][0], s[i][1]), fmaxf(s[i][2], s[i][3]));
            #pragma unroll
            for (int off = 8; off >= 1; off >>= 1)
                rm = fmaxf(rm, __shfl_xor_sync(0xffffffffu, rm, off));
            const float mn = fmaxf(m_i[i], rm);
            const float alpha = __expf(m_i[i] - mn);   // exp(-inf)=0 on first tile
            float p[4];
            float rs = 0.0f;
            #pragma unroll
            for (int jj = 0; jj < 4; jj++) {
                p[jj] = __expf(s[i][jj] - mn);          // masked -> exp(-inf)=0
                rs += p[jj];
            }
            #pragma unroll
            for (int off = 8; off >= 1; off >>= 1)
                rs += __shfl_xor_sync(0xffffffffu, rs, off);
            l_i[i] = l_i[i] * alpha + rs;
            m_i[i] = mn;
            #pragma unroll
            for (int jj = 0; jj < 4; jj++) acc[i][jj] *= alpha;
            #pragma unroll
            for (int jj = 0; jj < 4; jj++)
                Ps[(ty * 8 + i) * ATT_LD + tx * 4 + jj] = p[jj];
        }
        __syncthreads();

        // O += P V  (128x64 @ 64x64)
        #pragma unroll 8
        for (int kk = 0; kk < 64; kk++) {
            float pi[8], vj[4];
            #pragma unroll
            for (int i = 0; i < 8; i++) pi[i] = Ps[(ty * 8 + i) * ATT_LD + kk];
            #pragma unroll
            for (int jj = 0; jj < 4; jj++) vj[jj] = Vs[kk * ATT_LD + tx * 4 + jj];
            #pragma unroll
            for (int i = 0; i < 8; i++)
                #pragma unroll
                for (int jj = 0; jj < 4; jj++)
                    acc[i][jj] = fmaf(pi[i], vj[jj], acc[i][jj]);
        }
    }

    // Epilogue: O / l -> g_y [B,S,E]
    #pragma unroll
    for (int i = 0; i < 8; i++) {
        const float inv = 1.0f / l_i[i];
        const int qg = q0 + ty * 8 + i;
        const size_t row = ((size_t)(b * Ss + qg)) * Ee + h * 64;
        #pragma unroll
        for (int jj = 0; jj < 4; jj++)
            g_y[row + tx * 4 + jj] = acc[i][jj] * inv;
    }
}

// ---------------------------------------------------------------------------
// Kernel 3: out = y @ W_proj + b_proj
// (byte-identical to the R1-passing version)
// ---------------------------------------------------------------------------
__global__ __launch_bounds__(256) void proj_gemm_kernel(
    const float* __restrict__ W,      // [E, E]
    const float* __restrict__ bias,   // [E]
    float* __restrict__ out)          // [M, E]
{
    __shared__ float As[BK][BM + 1];
    __shared__ float Bs[BK][BN];

    const int tid = threadIdx.x;
    const int tx = tid & 15;
    const int ty = tid >> 4;
    const int m0 = blockIdx.y * BM;
    const int n0 = blockIdx.x * BN;

    float acc[4][4] = {};

    for (int k0 = 0; k0 < Ee; k0 += BK) {
        {
            const int row = tid >> 2;
            const int seg = tid & 3;
            const float4 v4 = *reinterpret_cast<const float4*>(
                g_y + (size_t)(m0 + row) * Ee + k0 + seg * 4);
            As[seg * 4 + 0][row] = v4.x;
            As[seg * 4 + 1][row] = v4.y;
            As[seg * 4 + 2][row] = v4.z;
            As[seg * 4 + 3][row] = v4.w;
        }
        {
            const int row = tid >> 4;
            const int c4 = tid & 15;
            const float4 v4 = *reinterpret_cast<const float4*>(
                W + (size_t)(k0 + row) * Ee + n0 + c4 * 4);
            Bs[row][c4 * 4 + 0] = v4.x;
            Bs[row][c4 * 4 + 1] = v4.y;
            Bs[row][c4 * 4 + 2] = v4.z;
            Bs[row][c4 * 4 + 3] = v4.w;
        }
        __syncthreads();

        #pragma unroll
        for (int kk = 0; kk < BK; kk++) {
            float a[4], bb[4];
            #pragma unroll
            for (int i = 0; i < 4; i++) a[i] = As[kk][ty * 4 + i];
            #pragma unroll
            for (int j = 0; j < 4; j++) bb[j] = Bs[kk][tx * 4 + j];
            #pragma unroll
            for (int i = 0; i < 4; i++)
                #pragma unroll
                for (int j = 0; j < 4; j++)
                    acc[i][j] = fmaf(a[i], bb[j], acc[i][j]);
        }
        __syncthreads();
    }

    #pragma unroll
    for (int i = 0; i < 4; i++) {
        const int m = m0 + ty * 4 + i;
        #pragma unroll
        for (int j = 0; j < 4; j++) {
            const int n = n0 + tx * 4 + j;
            out[(size_t)m * Ee + n] = acc[i][j] + bias[n];
        }
    }
}

// ---------------------------------------------------------------------------
// Launch
// ---------------------------------------------------------------------------
extern "C" void kernel_launch(void* const* d_in, const int* in_sizes, int n_in,
                              void* d_out, int out_size)
{
    const float* x      = (const float*)d_in[0];  // [B,S,E]
    const float* W_attn = (const float*)d_in[1];  // [E,3E]
    const float* b_attn = (const float*)d_in[2];  // [3E]
    const float* W_proj = (const float*)d_in[3];  // [E,E]
    const float* b_proj = (const float*)d_in[4];  // [E]
    const int* att_mask = (const int*)d_in[5];    // [B,S]
    float* out = (float*)d_out;

    // Opt-in to >48KB dynamic smem for the attention kernel (idempotent)
    cudaFuncSetAttribute(attn_kernel,
                         cudaFuncAttributeMaxDynamicSharedMemorySize,
                         (int)ATT_SMEM_BYTES);

    {
        dim3 grid(N_QKV / BN, Mrows / BM);   // 36 x 128
        qkv_gemm_kernel<<<grid, 256>>>(x, W_attn, b_attn);
    }
    {
        dim3 grid(Ss / QROWS, Hh, Bb);       // 16 x 12 x 4
        attn_kernel<<<grid, 256, ATT_SMEM_BYTES>>>(att_mask);
    }
    {
        dim3 grid(Ee / BN, Mrows / BM);      // 12 x 128
        proj_gemm_kernel<<<grid, 256>>>(W_proj, b_proj, out);
    }
}

// round 10
// speedup vs baseline: 1.1843x; 1.1347x over previous
#include <cuda_runtime.h>
#include <math.h>

// Problem constants
constexpr int Bb = 4;
constexpr int Ss = 2048;
constexpr int Ee = 768;
constexpr int Hh = 12;
constexpr int Dd = 64;
constexpr int Mrows = Bb * Ss;      // 8192
constexpr int N_QKV = 3 * Ee;       // 2304

// GEMM tiling: 128x128 block, BK=16, 256 threads, 8x8 per thread
constexpr int TBM = 128, TBN = 128, TBK = 16;

// Scratch (device globals: no allocation allowed)
__device__ float g_q[(size_t)Bb * Hh * Ss * Dd];
__device__ float g_k[(size_t)Bb * Hh * Ss * Dd];
__device__ float g_v[(size_t)Bb * Hh * Ss * Dd];
__device__ float g_y[(size_t)Bb * Ss * Ee];

// ---------------------------------------------------------------------------
// Kernel 1: QKV = x @ W_attn + b_attn, scattered to [B,H,S,D] q/k/v buffers
// 128x128x16 tiles, 8x8 microtile (64 FMA : 4 LDS.128 per thread per k)
// ---------------------------------------------------------------------------
__global__ __launch_bounds__(256) void qkv_gemm_kernel(
    const float* __restrict__ x,      // [M, E]
    const float* __restrict__ W,      // [E, 3E]
    const float* __restrict__ bias)   // [3E]
{
    __shared__ float As[TBK][TBM + 4];   // transposed: As[k][m]
    __shared__ float Bs[TBK][TBN + 4];

    const int tid = threadIdx.x;
    const int tx = tid & 15;        // 0..15 (n)
    const int ty = tid >> 4;        // 0..15 (m)
    const int m0 = blockIdx.y * TBM;
    const int n0 = blockIdx.x * TBN;

    float acc[8][8] = {};

    for (int k0 = 0; k0 < Ee; k0 += TBK) {
        // A tile 128x16 = 512 float4, 2 per thread; store transposed
        #pragma unroll
        for (int q = 0; q < 2; q++) {
            const int id = q * 256 + tid;
            const int r = id >> 2;          // 0..127
            const int seg = id & 3;         // 0..3
            const float4 v4 = *reinterpret_cast<const float4*>(
                x + (size_t)(m0 + r) * Ee + k0 + seg * 4);
            As[seg * 4 + 0][r] = v4.x;
            As[seg * 4 + 1][r] = v4.y;
            As[seg * 4 + 2][r] = v4.z;
            As[seg * 4 + 3][r] = v4.w;
        }
        // B tile 16x128 = 512 float4, 2 per thread
        #pragma unroll
        for (int q = 0; q < 2; q++) {
            const int id = q * 256 + tid;
            const int r = id >> 5;          // 0..15
            const int c4 = id & 31;         // 0..31
            const float4 v4 = *reinterpret_cast<const float4*>(
                W + (size_t)(k0 + r) * N_QKV + n0 + c4 * 4);
            *reinterpret_cast<float4*>(&Bs[r][c4 * 4]) = v4;
        }
        __syncthreads();

        #pragma unroll
        for (int kk = 0; kk < TBK; kk++) {
            float a[8], b[8];
            *reinterpret_cast<float4*>(&a[0]) = *reinterpret_cast<const float4*>(&As[kk][ty * 8]);
            *reinterpret_cast<float4*>(&a[4]) = *reinterpret_cast<const float4*>(&As[kk][ty * 8 + 4]);
            *reinterpret_cast<float4*>(&b[0]) = *reinterpret_cast<const float4*>(&Bs[kk][tx * 8]);
            *reinterpret_cast<float4*>(&b[4]) = *reinterpret_cast<const float4*>(&Bs[kk][tx * 8 + 4]);
            #pragma unroll
            for (int i = 0; i < 8; i++)
                #pragma unroll
                for (int j = 0; j < 8; j++)
                    acc[i][j] = fmaf(a[i], b[j], acc[i][j]);
        }
        __syncthreads();
    }

    // Epilogue: bias + scatter into [B,H,S,D], float4 stores (4-elem runs stay
    // inside one 64-wide head since n is 4-aligned and 64 | head boundaries;
    // 768 % 128 == 0 so a block never straddles the q/k/v boundary).
    float bb[8];
    #pragma unroll
    for (int j = 0; j < 8; j++) bb[j] = bias[n0 + tx * 8 + j];

    #pragma unroll
    for (int i = 0; i < 8; i++) {
        const int m = m0 + ty * 8 + i;
        const int b = m >> 11;          // / 2048
        const int s = m & 2047;
        #pragma unroll
        for (int half = 0; half < 2; half++) {
            const int n = n0 + tx * 8 + half * 4;
            float4 o;
            o.x = acc[i][half * 4 + 0] + bb[half * 4 + 0];
            o.y = acc[i][half * 4 + 1] + bb[half * 4 + 1];
            o.z = acc[i][half * 4 + 2] + bb[half * 4 + 2];
            o.w = acc[i][half * 4 + 3] + bb[half * 4 + 3];
            const int which = n / Ee;   // 0=q, 1=k, 2=v
            const int e = n - which * Ee;
            const int h = e >> 6;
            const int d = e & 63;
            float* dst = (which == 0) ? g_q : (which == 1) ? g_k : g_v;
            *reinterpret_cast<float4*>(
                dst + (((size_t)(b * Hh + h)) * Ss + s) * Dd + d) = o;
        }
    }
}

// ---------------------------------------------------------------------------
// Kernel 2: flash-style causal attention, 128-query x 64-key tiles.
// (byte-identical to the R9-passing version)
// ---------------------------------------------------------------------------
constexpr int ATT_LD = 65;
constexpr int QROWS = 128;
constexpr size_t ATT_SMEM_BYTES =
    (size_t)(QROWS * ATT_LD + 64 * ATT_LD + 64 * ATT_LD + QROWS * ATT_LD) * sizeof(float); // 99840

__global__ __launch_bounds__(256) void attn_kernel(const int* __restrict__ att_mask)
{
    extern __shared__ float sm[];
    float* Qs = sm;                                    // [128][65]
    float* Ks = sm + QROWS * ATT_LD;                   // [64][65]
    float* Vs = sm + QROWS * ATT_LD + 64 * ATT_LD;     // [64][65]
    float* Ps = sm + QROWS * ATT_LD + 2 * 64 * ATT_LD; // [128][65]

    const int tid = threadIdx.x;
    const int tx = tid & 15;
    const int ty = tid >> 4;
    const int qb = blockIdx.x;          // 0..15
    const int h = blockIdx.y;
    const int b = blockIdx.z;
    const size_t head_base = ((size_t)(b * Hh + h)) * Ss * Dd;
    const int q0 = qb * QROWS;

    // Load Q tile [128][64] -> Qs (2048 float4, 8 per thread)
    #pragma unroll
    for (int p = 0; p < 8; p++) {
        const int lin = p * 256 + tid;
        const int r = lin >> 4;
        const int c4 = lin & 15;
        const float4 v4 = *reinterpret_cast<const float4*>(
            g_q + head_base + (size_t)(q0 + r) * Dd + c4 * 4);
        Qs[r * ATT_LD + c4 * 4 + 0] = v4.x;
        Qs[r * ATT_LD + c4 * 4 + 1] = v4.y;
        Qs[r * ATT_LD + c4 * 4 + 2] = v4.z;
        Qs[r * ATT_LD + c4 * 4 + 3] = v4.w;
    }

    float m_i[8], l_i[8];
    float acc[8][4] = {};
    #pragma unroll
    for (int i = 0; i < 8; i++) { m_i[i] = -INFINITY; l_i[i] = 0.0f; }

    const int jmax = 2 * qb + 1;        // last key tile overlapping this q tile
    for (int j = 0; j <= jmax; j++) {
        __syncthreads();  // previous iteration done reading Ks/Vs/Ps
        // Load K and V tiles for key rows [j*64, j*64+64)
        #pragma unroll
        for (int p = 0; p < 4; p++) {
            const int lin = p * 256 + tid;
            const int r = lin >> 4;
            const int c4 = lin & 15;
            const size_t off = head_base + (size_t)(j * 64 + r) * Dd + c4 * 4;
            const float4 k4 = *reinterpret_cast<const float4*>(g_k + off);
            const float4 v4 = *reinterpret_cast<const float4*>(g_v + off);
            Ks[r * ATT_LD + c4 * 4 + 0] = k4.x;
            Ks[r * ATT_LD + c4 * 4 + 1] = k4.y;
            Ks[r * ATT_LD + c4 * 4 + 2] = k4.z;
            Ks[r * ATT_LD + c4 * 4 + 3] = k4.w;
            Vs[r * ATT_LD + c4 * 4 + 0] = v4.x;
            Vs[r * ATT_LD + c4 * 4 + 1] = v4.y;
            Vs[r * ATT_LD + c4 * 4 + 2] = v4.z;
            Vs[r * ATT_LD + c4 * 4 + 3] = v4.w;
        }
        __syncthreads();

        // S = Q K^T (128x64), each thread 8x4
        float s[8][4] = {};
        #pragma unroll 8
        for (int kk = 0; kk < Dd; kk++) {
            float a[8], bbk[4];
            #pragma unroll
            for (int i = 0; i < 8; i++) a[i] = Qs[(ty * 8 + i) * ATT_LD + kk];
            #pragma unroll
            for (int jj = 0; jj < 4; jj++) bbk[jj] = Ks[(tx * 4 + jj) * ATT_LD + kk];
            #pragma unroll
            for (int i = 0; i < 8; i++)
                #pragma unroll
                for (int jj = 0; jj < 4; jj++)
                    s[i][jj] = fmaf(a[i], bbk[jj], s[i][jj]);
        }

        // Scale + causal + att_mask
        const int kbase = j * 64 + tx * 4;
        int mk[4];
        #pragma unroll
        for (int jj = 0; jj < 4; jj++) mk[jj] = att_mask[b * Ss + kbase + jj];

        #pragma unroll
        for (int i = 0; i < 8; i++) {
            const int qg = q0 + ty * 8 + i;
            #pragma unroll
            for (int jj = 0; jj < 4; jj++) {
                const int kg = kbase + jj;
                s[i][jj] = (kg <= qg && mk[jj] != 0) ? s[i][jj] * 0.125f : -INFINITY;
            }
        }

        // Online softmax (reduction across the 16 lanes sharing a q-row)
        #pragma unroll
        for (int i = 0; i < 8; i++) {
            float rm = fmaxf(fmaxf(s[i][0], s[i][1]), fmaxf(s[i][2], s[i][3]));
            #pragma unroll
            for (int off = 8; off >= 1; off >>= 1)
                rm = fmaxf(rm, __shfl_xor_sync(0xffffffffu, rm, off));
            const float mn = fmaxf(m_i[i], rm);
            const float alpha = __expf(m_i[i] - mn);   // exp(-inf)=0 on first tile
            float p[4];
            float rs = 0.0f;
            #pragma unroll
            for (int jj = 0; jj < 4; jj++) {
                p[jj] = __expf(s[i][jj] - mn);          // masked -> exp(-inf)=0
                rs += p[jj];
            }
            #pragma unroll
            for (int off = 8; off >= 1; off >>= 1)
                rs += __shfl_xor_sync(0xffffffffu, rs, off);
            l_i[i] = l_i[i] * alpha + rs;
            m_i[i] = mn;
            #pragma unroll
            for (int jj = 0; jj < 4; jj++) acc[i][jj] *= alpha;
            #pragma unroll
            for (int jj = 0; jj < 4; jj++)
                Ps[(ty * 8 + i) * ATT_LD + tx * 4 + jj] = p[jj];
        }
        __syncthreads();

        // O += P V  (128x64 @ 64x64)
        #pragma unroll 8
        for (int kk = 0; kk < 64; kk++) {
            float pi[8], vj[4];
            #pragma unroll
            for (int i = 0; i < 8; i++) pi[i] = Ps[(ty * 8 + i) * ATT_LD + kk];
            #pragma unroll
            for (int jj = 0; jj < 4; jj++) vj[jj] = Vs[kk * ATT_LD + tx * 4 + jj];
            #pragma unroll
            for (int i = 0; i < 8; i++)
                #pragma unroll
                for (int jj = 0; jj < 4; jj++)
                    acc[i][jj] = fmaf(pi[i], vj[jj], acc[i][jj]);
        }
    }

    // Epilogue: O / l -> g_y [B,S,E]
    #pragma unroll
    for (int i = 0; i < 8; i++) {
        const float inv = 1.0f / l_i[i];
        const int qg = q0 + ty * 8 + i;
        const size_t row = ((size_t)(b * Ss + qg)) * Ee + h * 64;
        #pragma unroll
        for (int jj = 0; jj < 4; jj++)
            g_y[row + tx * 4 + jj] = acc[i][jj] * inv;
    }
}

// ---------------------------------------------------------------------------
// Kernel 3: out = y @ W_proj + b_proj  (same 128x128x16 / 8x8 body)
// ---------------------------------------------------------------------------
__global__ __launch_bounds__(256) void proj_gemm_kernel(
    const float* __restrict__ W,      // [E, E]
    const float* __restrict__ bias,   // [E]
    float* __restrict__ out)          // [M, E]
{
    __shared__ float As[TBK][TBM + 4];
    __shared__ float Bs[TBK][TBN + 4];

    const int tid = threadIdx.x;
    const int tx = tid & 15;
    const int ty = tid >> 4;
    const int m0 = blockIdx.y * TBM;
    const int n0 = blockIdx.x * TBN;

    float acc[8][8] = {};

    for (int k0 = 0; k0 < Ee; k0 += TBK) {
        #pragma unroll
        for (int q = 0; q < 2; q++) {
            const int id = q * 256 + tid;
            const int r = id >> 2;
            const int seg = id & 3;
            const float4 v4 = *reinterpret_cast<const float4*>(
                g_y + (size_t)(m0 + r) * Ee + k0 + seg * 4);
            As[seg * 4 + 0][r] = v4.x;
            As[seg * 4 + 1][r] = v4.y;
            As[seg * 4 + 2][r] = v4.z;
            As[seg * 4 + 3][r] = v4.w;
        }
        #pragma unroll
        for (int q = 0; q < 2; q++) {
            const int id = q * 256 + tid;
            const int r = id >> 5;
            const int c4 = id & 31;
            const float4 v4 = *reinterpret_cast<const float4*>(
                W + (size_t)(k0 + r) * Ee + n0 + c4 * 4);
            *reinterpret_cast<float4*>(&Bs[r][c4 * 4]) = v4;
        }
        __syncthreads();

        #pragma unroll
        for (int kk = 0; kk < TBK; kk++) {
            float a[8], b[8];
            *reinterpret_cast<float4*>(&a[0]) = *reinterpret_cast<const float4*>(&As[kk][ty * 8]);
            *reinterpret_cast<float4*>(&a[4]) = *reinterpret_cast<const float4*>(&As[kk][ty * 8 + 4]);
            *reinterpret_cast<float4*>(&b[0]) = *reinterpret_cast<const float4*>(&Bs[kk][tx * 8]);
            *reinterpret_cast<float4*>(&b[4]) = *reinterpret_cast<const float4*>(&Bs[kk][tx * 8 + 4]);
            #pragma unroll
            for (int i = 0; i < 8; i++)
                #pragma unroll
                for (int j = 0; j < 8; j++)
                    acc[i][j] = fmaf(a[i], b[j], acc[i][j]);
        }
        __syncthreads();
    }

    float bb[8];
    #pragma unroll
    for (int j = 0; j < 8; j++) bb[j] = bias[n0 + tx * 8 + j];

    #pragma unroll
    for (int i = 0; i < 8; i++) {
        const int m = m0 + ty * 8 + i;
        #pragma unroll
        for (int half = 0; half < 2; half++) {
            const int n = n0 + tx * 8 + half * 4;
            float4 o;
            o.x = acc[i][half * 4 + 0] + bb[half * 4 + 0];
            o.y = acc[i][half * 4 + 1] + bb[half * 4 + 1];
            o.z = acc[i][half * 4 + 2] + bb[half * 4 + 2];
            o.w = acc[i][half * 4 + 3] + bb[half * 4 + 3];
            *reinterpret_cast<float4*>(out + (size_t)m * Ee + n) = o;
        }
    }
}

// ---------------------------------------------------------------------------
// Launch
// ---------------------------------------------------------------------------
extern "C" void kernel_launch(void* const* d_in, const int* in_sizes, int n_in,
                              void* d_out, int out_size)
{
    const float* x      = (const float*)d_in[0];  // [B,S,E]
    const float* W_attn = (const float*)d_in[1];  // [E,3E]
    const float* b_attn = (const float*)d_in[2];  // [3E]
    const float* W_proj = (const float*)d_in[3];  // [E,E]
    const float* b_proj = (const float*)d_in[4];  // [E]
    const int* att_mask = (const int*)d_in[5];    // [B,S]
    float* out = (float*)d_out;

    // Opt-in to >48KB dynamic smem for the attention kernel (idempotent)
    cudaFuncSetAttribute(attn_kernel,
                         cudaFuncAttributeMaxDynamicSharedMemorySize,
                         (int)ATT_SMEM_BYTES);

    {
        dim3 grid(N_QKV / TBN, Mrows / TBM);   // 18 x 64
        qkv_gemm_kernel<<<grid, 256>>>(x, W_attn, b_attn);
    }
    {
        dim3 grid(Ss / QROWS, Hh, Bb);         // 16 x 12 x 4
        attn_kernel<<<grid, 256, ATT_SMEM_BYTES>>>(att_mask);
    }
    {
        dim3 grid(Ee / TBN, Mrows / TBM);      // 6 x 64
        proj_gemm_kernel<<<grid, 256>>>(W_proj, b_proj, out);
    }
}

// round 11
// speedup vs baseline: 1.3383x; 1.1300x over previous
#include <cuda_runtime.h>
#include <cuda_bf16.h>
#include <math.h>
#include <stdint.h>

// Problem constants
constexpr int Bb = 4;
constexpr int Ss = 2048;
constexpr int Ee = 768;
constexpr int Hh = 12;
constexpr int Dd = 64;
constexpr int Mrows = Bb * Ss;      // 8192
constexpr int N_QKV = 3 * Ee;       // 2304
constexpr int Kdim = 768;

// Scratch (device globals: no allocation allowed)
__device__ float g_q[(size_t)Bb * Hh * Ss * Dd];
__device__ float g_k[(size_t)Bb * Hh * Ss * Dd];
__device__ float g_v[(size_t)Bb * Hh * Ss * Dd];
__device__ float g_y[(size_t)Bb * Ss * Ee];

// ---------------------------------------------------------------------------
// Raw-PTX bf16-split GEMM pieces (shared by the two plain kernels below).
// A = Ah + Al (bf16 split), B likewise. acc += Ah*Bh + Ah*Bl + Al*Bh (f32).
// mma.sync.aligned.m16n8k16.row.col.f32.bf16.bf16.f32
// Block 128x64, BK=32. 8 warps (4x2), warp tile 32x32 = 2(m16) x 4(n8).
// B staged TRANSPOSED in smem ([n][k]) so B-fragment loads are aligned b32 LDS.
// ---------------------------------------------------------------------------
constexpr int GBM = 128, GBN = 64, GBK = 32;
constexpr int A_LD  = GBK + 8;   // 40 bf16 elems per A row (conflict-free frag loads)
constexpr int BT_LD = GBK + 8;   // 40 bf16 elems per Bt row

__device__ __forceinline__ uint32_t pack2(float v0, float v1) {
    __nv_bfloat162 t = __floats2bfloat162_rn(v0, v1);  // x=v0 (low), y=v1 (high)
    return *reinterpret_cast<uint32_t*>(&t);
}

__device__ __forceinline__ void mma_bf16(float d[4],
                                         const uint32_t a[4],
                                         const uint32_t b[2]) {
    asm volatile(
        "mma.sync.aligned.m16n8k16.row.col.f32.bf16.bf16.f32 "
        "{%0,%1,%2,%3}, {%4,%5,%6,%7}, {%8,%9}, {%0,%1,%2,%3};\n"
        : "+f"(d[0]), "+f"(d[1]), "+f"(d[2]), "+f"(d[3])
        : "r"(a[0]), "r"(a[1]), "r"(a[2]), "r"(a[3]),
          "r"(b[0]), "r"(b[1]));
}

// ---------------------------------------------------------------------------
// Kernel 1: QKV = x @ W_attn + b_attn, scattered to [B,H,S,D] (plain kernel)
// ---------------------------------------------------------------------------
__global__ __launch_bounds__(256) void qkv_gemm_kernel(
    const float* __restrict__ x,      // [M, 768]
    const float* __restrict__ W,      // [768, 2304]
    const float* __restrict__ bias)   // [2304]
{
    __shared__ __nv_bfloat16 Ah[GBM * A_LD];
    __shared__ __nv_bfloat16 Al[GBM * A_LD];
    __shared__ __nv_bfloat16 Bth[GBN * BT_LD];
    __shared__ __nv_bfloat16 Btl[GBN * BT_LD];

    const int tid = threadIdx.x;
    const int m0 = blockIdx.y * GBM;
    const int n0 = blockIdx.x * GBN;

    const int w    = tid >> 5;
    const int wm   = w >> 1;       // 0..3
    const int wn   = w & 1;        // 0..1
    const int lane = tid & 31;
    const int g    = lane >> 2;    // 0..7
    const int tg   = lane & 3;     // 0..3

    float acc[2][4][4] = {};

    for (int k0 = 0; k0 < Kdim; k0 += GBK) {
        // A tile 128x32 (1024 float4, 4/thread); split -> Ah/Al
        #pragma unroll
        for (int p = 0; p < 4; p++) {
            const int id = p * 256 + tid;
            const int r = id >> 3;
            const int c4 = id & 7;
            const float4 v4 = *reinterpret_cast<const float4*>(
                x + (size_t)(m0 + r) * Kdim + k0 + c4 * 4);
            const float vv[4] = {v4.x, v4.y, v4.z, v4.w};
            float hi[4], lo[4];
            #pragma unroll
            for (int q = 0; q < 4; q++) {
                hi[q] = __bfloat162float(__float2bfloat16(vv[q]));
                lo[q] = vv[q] - hi[q];
            }
            uint32_t* ah32 = reinterpret_cast<uint32_t*>(Ah + r * A_LD + c4 * 4);
            uint32_t* al32 = reinterpret_cast<uint32_t*>(Al + r * A_LD + c4 * 4);
            ah32[0] = pack2(hi[0], hi[1]); ah32[1] = pack2(hi[2], hi[3]);
            al32[0] = pack2(lo[0], lo[1]); al32[1] = pack2(lo[2], lo[3]);
        }
        // B tile 32x64 (512 float4, 2/thread); split -> transposed
        #pragma unroll
        for (int p = 0; p < 2; p++) {
            const int id = p * 256 + tid;
            const int r = id >> 4;
            const int c4 = id & 15;
            const float4 v4 = *reinterpret_cast<const float4*>(
                W + (size_t)(k0 + r) * N_QKV + n0 + c4 * 4);
            const float vv[4] = {v4.x, v4.y, v4.z, v4.w};
            #pragma unroll
            for (int q = 0; q < 4; q++) {
                const float h = __bfloat162float(__float2bfloat16(vv[q]));
                const float l = vv[q] - h;
                Bth[(c4 * 4 + q) * BT_LD + r] = __float2bfloat16(h);
                Btl[(c4 * 4 + q) * BT_LD + r] = __float2bfloat16(l);
            }
        }
        __syncthreads();

        #pragma unroll
        for (int ks = 0; ks < 2; ks++) {
            const int kk = ks * 16;
            uint32_t ahf[2][4], alf[2][4];
            #pragma unroll
            for (int i = 0; i < 2; i++) {
                const int br = wm * 32 + i * 16;
                ahf[i][0] = *reinterpret_cast<const uint32_t*>(Ah + (br + g)     * A_LD + kk + tg * 2);
                ahf[i][1] = *reinterpret_cast<const uint32_t*>(Ah + (br + g + 8) * A_LD + kk + tg * 2);
                ahf[i][2] = *reinterpret_cast<const uint32_t*>(Ah + (br + g)     * A_LD + kk + tg * 2 + 8);
                ahf[i][3] = *reinterpret_cast<const uint32_t*>(Ah + (br + g + 8) * A_LD + kk + tg * 2 + 8);
                alf[i][0] = *reinterpret_cast<const uint32_t*>(Al + (br + g)     * A_LD + kk + tg * 2);
                alf[i][1] = *reinterpret_cast<const uint32_t*>(Al + (br + g + 8) * A_LD + kk + tg * 2);
                alf[i][2] = *reinterpret_cast<const uint32_t*>(Al + (br + g)     * A_LD + kk + tg * 2 + 8);
                alf[i][3] = *reinterpret_cast<const uint32_t*>(Al + (br + g + 8) * A_LD + kk + tg * 2 + 8);
            }
            uint32_t bhf[4][2], blf[4][2];
            #pragma unroll
            for (int j = 0; j < 4; j++) {
                const int n = wn * 32 + j * 8 + g;
                bhf[j][0] = *reinterpret_cast<const uint32_t*>(Bth + n * BT_LD + kk + tg * 2);
                bhf[j][1] = *reinterpret_cast<const uint32_t*>(Bth + n * BT_LD + kk + tg * 2 + 8);
                blf[j][0] = *reinterpret_cast<const uint32_t*>(Btl + n * BT_LD + kk + tg * 2);
                blf[j][1] = *reinterpret_cast<const uint32_t*>(Btl + n * BT_LD + kk + tg * 2 + 8);
            }
            #pragma unroll
            for (int i = 0; i < 2; i++)
                #pragma unroll
                for (int j = 0; j < 4; j++) {
                    mma_bf16(acc[i][j], ahf[i], bhf[j]);
                    mma_bf16(acc[i][j], ahf[i], blf[j]);
                    mma_bf16(acc[i][j], alf[i], bhf[j]);
                }
        }
        __syncthreads();
    }

    // Epilogue: bias + scatter into g_q/g_k/g_v [B,H,S,D]
    #pragma unroll
    for (int i = 0; i < 2; i++) {
        #pragma unroll
        for (int j = 0; j < 4; j++) {
            const int colb = n0 + wn * 32 + j * 8 + tg * 2;
            #pragma unroll
            for (int e4 = 0; e4 < 4; e4++) {
                const int m = m0 + wm * 32 + i * 16 + g + (e4 >= 2 ? 8 : 0);
                const int n = colb + (e4 & 1);
                const float val = acc[i][j][e4] + bias[n];
                const int b = m >> 11;
                const int s = m & 2047;
                const int which = n / Ee;       // 0=q,1=k,2=v
                const int e = n - which * Ee;
                const int h = e >> 6;
                const int d = e & 63;
                const size_t idx = (((size_t)(b * Hh + h)) * Ss + s) * Dd + d;
                float* dst = (which == 0) ? g_q : (which == 1) ? g_k : g_v;
                dst[idx] = val;
            }
        }
    }
}

// ---------------------------------------------------------------------------
// Kernel 2: flash-style causal attention (byte-identical to R10-passing)
// ---------------------------------------------------------------------------
constexpr int ATT_LD = 65;
constexpr int QROWS = 128;
constexpr size_t ATT_SMEM_BYTES =
    (size_t)(QROWS * ATT_LD + 64 * ATT_LD + 64 * ATT_LD + QROWS * ATT_LD) * sizeof(float); // 99840

__global__ __launch_bounds__(256) void attn_kernel(const int* __restrict__ att_mask)
{
    extern __shared__ float sm[];
    float* Qs = sm;                                    // [128][65]
    float* Ks = sm + QROWS * ATT_LD;                   // [64][65]
    float* Vs = sm + QROWS * ATT_LD + 64 * ATT_LD;     // [64][65]
    float* Ps = sm + QROWS * ATT_LD + 2 * 64 * ATT_LD; // [128][65]

    const int tid = threadIdx.x;
    const int tx = tid & 15;
    const int ty = tid >> 4;
    const int qb = blockIdx.x;          // 0..15
    const int h = blockIdx.y;
    const int b = blockIdx.z;
    const size_t head_base = ((size_t)(b * Hh + h)) * Ss * Dd;
    const int q0 = qb * QROWS;

    #pragma unroll
    for (int p = 0; p < 8; p++) {
        const int lin = p * 256 + tid;
        const int r = lin >> 4;
        const int c4 = lin & 15;
        const float4 v4 = *reinterpret_cast<const float4*>(
            g_q + head_base + (size_t)(q0 + r) * Dd + c4 * 4);
        Qs[r * ATT_LD + c4 * 4 + 0] = v4.x;
        Qs[r * ATT_LD + c4 * 4 + 1] = v4.y;
        Qs[r * ATT_LD + c4 * 4 + 2] = v4.z;
        Qs[r * ATT_LD + c4 * 4 + 3] = v4.w;
    }

    float m_i[8], l_i[8];
    float acc[8][4] = {};
    #pragma unroll
    for (int i = 0; i < 8; i++) { m_i[i] = -INFINITY; l_i[i] = 0.0f; }

    const int jmax = 2 * qb + 1;
    for (int j = 0; j <= jmax; j++) {
        __syncthreads();
        #pragma unroll
        for (int p = 0; p < 4; p++) {
            const int lin = p * 256 + tid;
            const int r = lin >> 4;
            const int c4 = lin & 15;
            const size_t off = head_base + (size_t)(j * 64 + r) * Dd + c4 * 4;
            const float4 k4 = *reinterpret_cast<const float4*>(g_k + off);
            const float4 v4 = *reinterpret_cast<const float4*>(g_v + off);
            Ks[r * ATT_LD + c4 * 4 + 0] = k4.x;
            Ks[r * ATT_LD + c4 * 4 + 1] = k4.y;
            Ks[r * ATT_LD + c4 * 4 + 2] = k4.z;
            Ks[r * ATT_LD + c4 * 4 + 3] = k4.w;
            Vs[r * ATT_LD + c4 * 4 + 0] = v4.x;
            Vs[r * ATT_LD + c4 * 4 + 1] = v4.y;
            Vs[r * ATT_LD + c4 * 4 + 2] = v4.z;
            Vs[r * ATT_LD + c4 * 4 + 3] = v4.w;
        }
        __syncthreads();

        float s[8][4] = {};
        #pragma unroll 8
        for (int kk = 0; kk < Dd; kk++) {
            float a[8], bbk[4];
            #pragma unroll
            for (int i = 0; i < 8; i++) a[i] = Qs[(ty * 8 + i) * ATT_LD + kk];
            #pragma unroll
            for (int jj = 0; jj < 4; jj++) bbk[jj] = Ks[(tx * 4 + jj) * ATT_LD + kk];
            #pragma unroll
            for (int i = 0; i < 8; i++)
                #pragma unroll
                for (int jj = 0; jj < 4; jj++)
                    s[i][jj] = fmaf(a[i], bbk[jj], s[i][jj]);
        }

        const int kbase = j * 64 + tx * 4;
        int mk[4];
        #pragma unroll
        for (int jj = 0; jj < 4; jj++) mk[jj] = att_mask[b * Ss + kbase + jj];

        #pragma unroll
        for (int i = 0; i < 8; i++) {
            const int qg = q0 + ty * 8 + i;
            #pragma unroll
            for (int jj = 0; jj < 4; jj++) {
                const int kg = kbase + jj;
                s[i][jj] = (kg <= qg && mk[jj] != 0) ? s[i][jj] * 0.125f : -INFINITY;
            }
        }

        #pragma unroll
        for (int i = 0; i < 8; i++) {
            float rm = fmaxf(fmaxf(s[i][0], s[i][1]), fmaxf(s[i][2], s[i][3]));
            #pragma unroll
            for (int off = 8; off >= 1; off >>= 1)
                rm = fmaxf(rm, __shfl_xor_sync(0xffffffffu, rm, off));
            const float mn = fmaxf(m_i[i], rm);
            const float alpha = __expf(m_i[i] - mn);
            float p[4];
            float rs = 0.0f;
            #pragma unroll
            for (int jj = 0; jj < 4; jj++) {
                p[jj] = __expf(s[i][jj] - mn);
                rs += p[jj];
            }
            #pragma unroll
            for (int off = 8; off >= 1; off >>= 1)
                rs += __shfl_xor_sync(0xffffffffu, rs, off);
            l_i[i] = l_i[i] * alpha + rs;
            m_i[i] = mn;
            #pragma unroll
            for (int jj = 0; jj < 4; jj++) acc[i][jj] *= alpha;
            #pragma unroll
            for (int jj = 0; jj < 4; jj++)
                Ps[(ty * 8 + i) * ATT_LD + tx * 4 + jj] = p[jj];
        }
        __syncthreads();

        #pragma unroll 8
        for (int kk = 0; kk < 64; kk++) {
            float pi[8], vj[4];
            #pragma unroll
            for (int i = 0; i < 8; i++) pi[i] = Ps[(ty * 8 + i) * ATT_LD + kk];
            #pragma unroll
            for (int jj = 0; jj < 4; jj++) vj[jj] = Vs[kk * ATT_LD + tx * 4 + jj];
            #pragma unroll
            for (int i = 0; i < 8; i++)
                #pragma unroll
                for (int jj = 0; jj < 4; jj++)
                    acc[i][jj] = fmaf(pi[i], vj[jj], acc[i][jj]);
        }
    }

    #pragma unroll
    for (int i = 0; i < 8; i++) {
        const float inv = 1.0f / l_i[i];
        const int qg = q0 + ty * 8 + i;
        const size_t row = ((size_t)(b * Ss + qg)) * Ee + h * 64;
        #pragma unroll
        for (int jj = 0; jj < 4; jj++)
            g_y[row + tx * 4 + jj] = acc[i][jj] * inv;
    }
}

// ---------------------------------------------------------------------------
// Kernel 3: out = y @ W_proj + b_proj (plain kernel, same mma body)
// ---------------------------------------------------------------------------
__global__ __launch_bounds__(256) void proj_gemm_kernel(
    const float* __restrict__ W,      // [768, 768]
    const float* __restrict__ bias,   // [768]
    float* __restrict__ out)          // [M, 768]
{
    __shared__ __nv_bfloat16 Ah[GBM * A_LD];
    __shared__ __nv_bfloat16 Al[GBM * A_LD];
    __shared__ __nv_bfloat16 Bth[GBN * BT_LD];
    __shared__ __nv_bfloat16 Btl[GBN * BT_LD];

    const int tid = threadIdx.x;
    const int m0 = blockIdx.y * GBM;
    const int n0 = blockIdx.x * GBN;

    const int w    = tid >> 5;
    const int wm   = w >> 1;
    const int wn   = w & 1;
    const int lane = tid & 31;
    const int g    = lane >> 2;
    const int tg   = lane & 3;

    float acc[2][4][4] = {};

    for (int k0 = 0; k0 < Kdim; k0 += GBK) {
        #pragma unroll
        for (int p = 0; p < 4; p++) {
            const int id = p * 256 + tid;
            const int r = id >> 3;
            const int c4 = id & 7;
            const float4 v4 = *reinterpret_cast<const float4*>(
                g_y + (size_t)(m0 + r) * Kdim + k0 + c4 * 4);
            const float vv[4] = {v4.x, v4.y, v4.z, v4.w};
            float hi[4], lo[4];
            #pragma unroll
            for (int q = 0; q < 4; q++) {
                hi[q] = __bfloat162float(__float2bfloat16(vv[q]));
                lo[q] = vv[q] - hi[q];
            }
            uint32_t* ah32 = reinterpret_cast<uint32_t*>(Ah + r * A_LD + c4 * 4);
            uint32_t* al32 = reinterpret_cast<uint32_t*>(Al + r * A_LD + c4 * 4);
            ah32[0] = pack2(hi[0], hi[1]); ah32[1] = pack2(hi[2], hi[3]);
            al32[0] = pack2(lo[0], lo[1]); al32[1] = pack2(lo[2], lo[3]);
        }
        #pragma unroll
        for (int p = 0; p < 2; p++) {
            const int id = p * 256 + tid;
            const int r = id >> 4;
            const int c4 = id & 15;
            const float4 v4 = *reinterpret_cast<const float4*>(
                W + (size_t)(k0 + r) * Ee + n0 + c4 * 4);
            const float vv[4] = {v4.x, v4.y, v4.z, v4.w};
            #pragma unroll
            for (int q = 0; q < 4; q++) {
                const float h = __bfloat162float(__float2bfloat16(vv[q]));
                const float l = vv[q] - h;
                Bth[(c4 * 4 + q) * BT_LD + r] = __float2bfloat16(h);
                Btl[(c4 * 4 + q) * BT_LD + r] = __float2bfloat16(l);
            }
        }
        __syncthreads();

        #pragma unroll
        for (int ks = 0; ks < 2; ks++) {
            const int kk = ks * 16;
            uint32_t ahf[2][4], alf[2][4];
            #pragma unroll
            for (int i = 0; i < 2; i++) {
                const int br = wm * 32 + i * 16;
                ahf[i][0] = *reinterpret_cast<const uint32_t*>(Ah + (br + g)     * A_LD + kk + tg * 2);
                ahf[i][1] = *reinterpret_cast<const uint32_t*>(Ah + (br + g + 8) * A_LD + kk + tg * 2);
                ahf[i][2] = *reinterpret_cast<const uint32_t*>(Ah + (br + g)     * A_LD + kk + tg * 2 + 8);
                ahf[i][3] = *reinterpret_cast<const uint32_t*>(Ah + (br + g + 8) * A_LD + kk + tg * 2 + 8);
                alf[i][0] = *reinterpret_cast<const uint32_t*>(Al + (br + g)     * A_LD + kk + tg * 2);
                alf[i][1] = *reinterpret_cast<const uint32_t*>(Al + (br + g + 8) * A_LD + kk + tg * 2);
                alf[i][2] = *reinterpret_cast<const uint32_t*>(Al + (br + g)     * A_LD + kk + tg * 2 + 8);
                alf[i][3] = *reinterpret_cast<const uint32_t*>(Al + (br + g + 8) * A_LD + kk + tg * 2 + 8);
            }
            uint32_t bhf[4][2], blf[4][2];
            #pragma unroll
            for (int j = 0; j < 4; j++) {
                const int n = wn * 32 + j * 8 + g;
                bhf[j][0] = *reinterpret_cast<const uint32_t*>(Bth + n * BT_LD + kk + tg * 2);
                bhf[j][1] = *reinterpret_cast<const uint32_t*>(Bth + n * BT_LD + kk + tg * 2 + 8);
                blf[j][0] = *reinterpret_cast<const uint32_t*>(Btl + n * BT_LD + kk + tg * 2);
                blf[j][1] = *reinterpret_cast<const uint32_t*>(Btl + n * BT_LD + kk + tg * 2 + 8);
            }
            #pragma unroll
            for (int i = 0; i < 2; i++)
                #pragma unroll
                for (int j = 0; j < 4; j++) {
                    mma_bf16(acc[i][j], ahf[i], bhf[j]);
                    mma_bf16(acc[i][j], ahf[i], blf[j]);
                    mma_bf16(acc[i][j], alf[i], bhf[j]);
                }
        }
        __syncthreads();
    }

    #pragma unroll
    for (int i = 0; i < 2; i++) {
        #pragma unroll
        for (int j = 0; j < 4; j++) {
            const int colb = n0 + wn * 32 + j * 8 + tg * 2;
            #pragma unroll
            for (int e4 = 0; e4 < 4; e4++) {
                const int m = m0 + wm * 32 + i * 16 + g + (e4 >= 2 ? 8 : 0);
                const int n = colb + (e4 & 1);
                out[(size_t)m * Ee + n] = acc[i][j][e4] + bias[n];
            }
        }
    }
}

// ---------------------------------------------------------------------------
// Launch
// ---------------------------------------------------------------------------
extern "C" void kernel_launch(void* const* d_in, const int* in_sizes, int n_in,
                              void* d_out, int out_size)
{
    const float* x      = (const float*)d_in[0];  // [B,S,E]
    const float* W_attn = (const float*)d_in[1];  // [E,3E]
    const float* b_attn = (const float*)d_in[2];  // [3E]
    const float* W_proj = (const float*)d_in[3];  // [E,E]
    const float* b_proj = (const float*)d_in[4];  // [E]
    const int* att_mask = (const int*)d_in[5];    // [B,S]
    float* out = (float*)d_out;

    // Opt-in to >48KB dynamic smem for the attention kernel (idempotent)
    cudaFuncSetAttribute(attn_kernel,
                         cudaFuncAttributeMaxDynamicSharedMemorySize,
                         (int)ATT_SMEM_BYTES);

    {
        dim3 grid(N_QKV / GBN, Mrows / GBM);   // 36 x 64
        qkv_gemm_kernel<<<grid, 256>>>(x, W_attn, b_attn);
    }
    {
        dim3 grid(Ss / QROWS, Hh, Bb);         // 16 x 12 x 4
        attn_kernel<<<grid, 256, ATT_SMEM_BYTES>>>(att_mask);
    }
    {
        dim3 grid(Ee / GBN, Mrows / GBM);      // 12 x 64
        proj_gemm_kernel<<<grid, 256>>>(W_proj, b_proj, out);
    }
}